// round 15
// baseline (speedup 1.0000x reference)
#include <cuda_runtime.h>
#include <math.h>

#define T_LEN 8192
#define THREADS_SCAN 1024
#define NWARPS (THREADS_SCAN / 32)       // 32
#define PER (T_LEN / THREADS_SCAN)       // 8 elements per thread
#define DISCOUNT_BITS 0x3F7D70A4u        // 0.99f
#define EPS 1e-9f
#define MAX_ROWS 4096                    // B = 4096 in this problem

__device__ float g_rowsum[MAX_ROWS];
__device__ float g_rowinv[MAX_ROWS];
__device__ float g_mean;
// Per-thread replay state: incoming carry + packed done mask (8 bits used)
__device__ float         g_carry[MAX_ROWS * THREADS_SCAN];   // 16 MB
__device__ unsigned char g_mask [MAX_ROWS * THREADS_SCAN];   //  4 MB

// SA(m)  = sum_{k=1..m} 0.99^k,  SA2(m) = sum_{k=1..m} 0.99^(2k)
// m = number of elements processed before the first done flag (0..8).
__constant__ float c_SA[9] = {
    0.0f, 0.99f, 1.9701f, 2.940399f, 3.90099501f, 4.8519850599f,
    5.793465209301f, 6.72553055720799f, 7.64827525163591f
};
__constant__ float c_SA2[9] = {
    0.0f, 0.9801f, 1.94069601f, 2.882176159411f, 3.804920853839f,
    4.709302928848f, 5.595687800564f, 6.464433613552f, 7.315891384647f
};

// Branchless coefficient: a_i = done_i ? 0.0f : 0.99f, no predicates.
__device__ __forceinline__ float coeff(unsigned mask, int i)
{
    const unsigned t = (unsigned)(((int)(mask << (31 - i))) >> 31);
    return __uint_as_float(DISCOUNT_BITS & ~t);
}

// ---------------------------------------------------------------------------
// P1: per-row reverse affine scan -> per-thread carry + per-row stats.
// ret[t] = r[t] + a[t]*ret[t+1],  a[t] = 0.99*(1-done[t]), done binary.
// Stats via prefix-map moments; SA/SA2 are closed-form table lookups.
// ---------------------------------------------------------------------------
__global__ __launch_bounds__(THREADS_SCAN, 2)
void scan_stats_kernel(const float* __restrict__ rew,
                       const float* __restrict__ done)
{
    const int b = blockIdx.x;
    const size_t rowoff = (size_t)b * T_LEN;
    const float* r = rew + rowoff;
    const float* d = done + rowoff;

    const int j    = threadIdx.x;
    const int lane = j & 31;
    const int warp = j >> 5;
    const int tbase = T_LEN - PER * (j + 1);

    float rv[PER];
    unsigned mask = 0;   // bit i set -> done at local index i

#pragma unroll
    for (int k = 0; k < PER / 4; k++) {
        float4 rr = __ldcs((const float4*)(r + tbase) + k);
        float4 dd = __ldcs((const float4*)(d + tbase) + k);
        rv[4 * k + 0] = rr.x;
        rv[4 * k + 1] = rr.y;
        rv[4 * k + 2] = rr.z;
        rv[4 * k + 3] = rr.w;
        if (dd.x != 0.0f) mask |= (1u << (4 * k + 0));
        if (dd.y != 0.0f) mask |= (1u << (4 * k + 1));
        if (dd.z != 0.0f) mask |= (1u << (4 * k + 2));
        if (dd.w != 0.0f) mask |= (1u << (4 * k + 3));
    }

    // Compose map (t-descending) + B-dependent moment accumulators.
    float A = 1.0f, B = 0.0f;
    float SB = 0.0f, SAB = 0.0f, SB2 = 0.0f;
#pragma unroll
    for (int i = PER - 1; i >= 0; i--) {
        const float a = coeff(mask, i);
        B = fmaf(a, B, rv[i]);
        A = a * A;
        SB += B;
        SB2 = fmaf(B, B, SB2);
        SAB = fmaf(A, B, SAB);
    }
    // Data-independent moments from first-done position.
    const int m = __clz(mask) - 24;          // 8 when mask == 0
    const float SA  = c_SA[m];
    const float SA2 = c_SA2[m];

    // Intra-warp inclusive affine scan.
#pragma unroll
    for (int off = 1; off < 32; off <<= 1) {
        float a1 = __shfl_up_sync(0xffffffffu, A, off);
        float b1 = __shfl_up_sync(0xffffffffu, B, off);
        if (lane >= off) {
            B = fmaf(A, b1, B);
            A = A * a1;
        }
    }

    // Exclusive-within-warp map for this thread
    float Ae = __shfl_up_sync(0xffffffffu, A, 1);
    float Be = __shfl_up_sync(0xffffffffu, B, 1);
    if (lane == 0) { Ae = 1.0f; Be = 0.0f; }

    __shared__ float sWA[NWARPS];
    __shared__ float sWB[NWARPS];
    __shared__ float sWP[NWARPS];
    __shared__ float sRS[NWARPS];
    __shared__ float sRQ[NWARPS];

    if (lane == 31) { sWA[warp] = A; sWB[warp] = B; }
    __syncthreads();

    if (warp == 0) {
        float a  = sWA[lane];
        float bb = sWB[lane];
#pragma unroll
        for (int off = 1; off < 32; off <<= 1) {
            float a1 = __shfl_up_sync(0xffffffffu, a, off);
            float b1 = __shfl_up_sync(0xffffffffu, bb, off);
            if (lane >= off) {
                bb = fmaf(a, b1, bb);
                a = a * a1;
            }
        }
        sWP[lane] = bb;
    }
    __syncthreads();

    // Incoming value for this thread (row starts from y0 = 0)
    const float Bw = (warp == 0) ? 0.0f : sWP[warp - 1];
    const float yin = fmaf(Ae, Bw, Be);

    // Persist replay state for P2
    const size_t sidx = (size_t)b * THREADS_SCAN + j;
    g_carry[sidx] = yin;
    g_mask[sidx]  = (unsigned char)mask;

    // Closed-form chunk stats
    float lsum = fmaf(SA, yin, SB);
    float lsq  = fmaf(yin, fmaf(SA2, yin, 2.0f * SAB), SB2);

    // Deterministic block reduction of sum / sumsq
#pragma unroll
    for (int off = 16; off > 0; off >>= 1) {
        lsum += __shfl_down_sync(0xffffffffu, lsum, off);
        lsq  += __shfl_down_sync(0xffffffffu, lsq,  off);
    }
    if (lane == 0) { sRS[warp] = lsum; sRQ[warp] = lsq; }
    __syncthreads();
    if (warp == 0) {
        float s = sRS[lane];
        float q = sRQ[lane];
#pragma unroll
        for (int off = 16; off > 0; off >>= 1) {
            s += __shfl_down_sync(0xffffffffu, s, off);
            q += __shfl_down_sync(0xffffffffu, q, off);
        }
        if (lane == 0) {
            g_rowsum[b] = s;
            float var = (q - s * s * (1.0f / T_LEN)) * (1.0f / (T_LEN - 1));
            var = fmaxf(var, 0.0f);
            g_rowinv[b] = 1.0f / (sqrtf(var) + EPS);
        }
    }
}

// ---------------------------------------------------------------------------
// K2: row-sum reduction -> global mean. PDL: wait for P1 (gridsync), then
// trigger immediately so P2 can launch and overlap its loads with this
// reduction. P2 grid-syncs before reading g_mean.
// ---------------------------------------------------------------------------
__global__ __launch_bounds__(256)
void mean_kernel(int n_rows)
{
    cudaGridDependencySynchronize();            // P1 fully done
    cudaTriggerProgrammaticLaunchCompletion();  // let P2 launch now

    __shared__ double sd[8];
    const int j = threadIdx.x;
    const int lane = j & 31;
    const int warp = j >> 5;
    double acc = 0.0;
    for (int i = j; i < n_rows; i += 256)
        acc += (double)g_rowsum[i];
#pragma unroll
    for (int off = 16; off > 0; off >>= 1)
        acc += __shfl_down_sync(0xffffffffu, acc, off);
    if (lane == 0) sd[warp] = acc;
    __syncthreads();
    if (warp == 0) {
        double v = (lane < 8) ? sd[lane] : 0.0;
#pragma unroll
        for (int off = 4; off > 0; off >>= 1)
            v += __shfl_down_sync(0xffffffffu, v, off);
        if (lane == 0)
            g_mean = (float)(v / ((double)n_rows * (double)T_LEN));
    }
}

// ---------------------------------------------------------------------------
// P2: barrier-free replay + normalize + store. Launches (PDL) while the mean
// kernel is still reducing; everything loaded in the prologue is a P1
// product (safe: P2 cannot launch before mean's trigger, which follows
// mean's gridsync on P1). gridsync before consuming g_mean.
// ---------------------------------------------------------------------------
__global__ __launch_bounds__(THREADS_SCAN, 2)
void finalize_kernel(const float* __restrict__ rew,
                     float* __restrict__ out)
{
    const int b = blockIdx.x;
    const size_t rowoff = (size_t)b * T_LEN;
    const float* r = rew + rowoff;
    float* o = out + rowoff;

    const int j = threadIdx.x;
    const int tbase = T_LEN - PER * (j + 1);

    const size_t sidx = (size_t)b * THREADS_SCAN + j;
    float y = g_carry[sidx];
    const unsigned mask = g_mask[sidx];
    const float inv = g_rowinv[b];

    float rv[PER];
#pragma unroll
    for (int k = 0; k < PER / 4; k++) {
        float4 rr = __ldcs((const float4*)(r + tbase) + k);
        rv[4 * k + 0] = rr.x;
        rv[4 * k + 1] = rr.y;
        rv[4 * k + 2] = rr.z;
        rv[4 * k + 3] = rr.w;
    }

    cudaGridDependencySynchronize();   // mean kernel complete
    const float mean = g_mean;

#pragma unroll
    for (int k = PER / 4 - 1; k >= 0; k--) {
        float4 w;
        {
            const float a = coeff(mask, 4 * k + 3);
            y = fmaf(a, y, rv[4 * k + 3]);
            w.w = (y - mean) * inv;
        }
        {
            const float a = coeff(mask, 4 * k + 2);
            y = fmaf(a, y, rv[4 * k + 2]);
            w.z = (y - mean) * inv;
        }
        {
            const float a = coeff(mask, 4 * k + 1);
            y = fmaf(a, y, rv[4 * k + 1]);
            w.y = (y - mean) * inv;
        }
        {
            const float a = coeff(mask, 4 * k + 0);
            y = fmaf(a, y, rv[4 * k + 0]);
            w.x = (y - mean) * inv;
        }
        __stcs((float4*)(o + tbase) + k, w);
    }
}

extern "C" void kernel_launch(void* const* d_in, const int* in_sizes, int n_in,
                              void* d_out, int out_size)
{
    const float* rewards = (const float*)d_in[0];
    const float* dones   = (const float*)d_in[1];
    float* out = (float*)d_out;

    const int n = in_sizes[0];
    const int B = n / T_LEN;

    scan_stats_kernel<<<B, THREADS_SCAN>>>(rewards, dones);

    cudaLaunchAttribute attr[1];
    attr[0].id = cudaLaunchAttributeProgrammaticStreamSerialization;
    attr[0].val.programmaticStreamSerializationAllowed = 1;

    {   // mean kernel: PDL after P1
        cudaLaunchConfig_t cfg = {};
        cfg.gridDim = dim3(1);
        cfg.blockDim = dim3(256);
        cfg.dynamicSmemBytes = 0;
        cfg.stream = 0;
        cfg.attrs = attr;
        cfg.numAttrs = 1;
        cudaLaunchKernelEx(&cfg, mean_kernel, B);
    }
    {   // finalize: PDL after mean (launches at mean's trigger)
        cudaLaunchConfig_t cfg = {};
        cfg.gridDim = dim3(B);
        cfg.blockDim = dim3(THREADS_SCAN);
        cfg.dynamicSmemBytes = 0;
        cfg.stream = 0;
        cfg.attrs = attr;
        cfg.numAttrs = 1;
        cudaLaunchKernelEx(&cfg, finalize_kernel, rewards, out);
    }
}